// round 16
// baseline (speedup 1.0000x reference)
#include <cuda_runtime.h>
#include <cuda_bf16.h>

#define BATCH 128
#define DIM   4096

#define ROWB 144                 // bytes per A row (64B Ah + 64B Al + 16B pad)
#define OFF_A0 0                 // 256 * 144 = 36864
#define OFF_A1 36864
#define OFF_GSH 73728            // 3*256 float2 hi gates = 12288
#define OFF_GSL 86016            // 3*256 float2 lo gates = 12288
#define SMEM_BYTES 98304

typedef unsigned int u32;

__device__ __forceinline__ u32 smem_u32(const void* p) {
    u32 a;
    asm("{ .reg .u64 t; cvta.to.shared.u64 t, %1; cvt.u32.u64 %0, t; }"
        : "=r"(a) : "l"(p));
    return a;
}
__device__ __forceinline__ u32 pbf2(float lo, float hi) {
    __nv_bfloat162 h = __floats2bfloat162_rn(lo, hi);   // lo -> low 16 bits
    return *reinterpret_cast<u32*>(&h);
}
__device__ __forceinline__ void bsplit(float v, float& hi, float& lo) {
    __nv_bfloat16 h = __float2bfloat16(v);
    hi = __bfloat162float(h);
    lo = v - hi;                                        // exact in f32
}
__device__ __forceinline__ void ldm4(u32* r, u32 addr) {
    asm volatile(
        "ldmatrix.sync.aligned.m8n8.x4.shared.b16 {%0,%1,%2,%3}, [%4];"
        : "=r"(r[0]), "=r"(r[1]), "=r"(r[2]), "=r"(r[3]) : "r"(addr));
}
__device__ __forceinline__ void mma16816(float* d, const u32* a,
                                         u32 b0, u32 b1) {
    asm volatile(
        "mma.sync.aligned.m16n8k16.row.col.f32.bf16.bf16.f32 "
        "{%0,%1,%2,%3}, {%4,%5,%6,%7}, {%8,%9}, {%0,%1,%2,%3};"
        : "+f"(d[0]), "+f"(d[1]), "+f"(d[2]), "+f"(d[3])
        : "r"(a[0]), "r"(a[1]), "r"(a[2]), "r"(a[3]), "r"(b0), "r"(b1));
}

// Real embedding of complex 16x16 U into 32x32 W (K=2c+p rows, N=2kap+s cols):
//   W[2c][2k]=Ur, W[2c+1][2k]=-Ui, W[2c][2k+1]=Ui, W[2c+1][2k+1]=Ur
// A rows = 256 fibers, real K-cols: A[j][2c]=xr, A[j][2c+1]=xi (bf16 hi; lo +64B)
// D = A*W : yr at even n, yi at odd n. Split: D = Ah*Wh + Al*Wh + Ah*Wl.

__global__ __launch_bounds__(512, 1)
void ulayer_mma(const float* __restrict__ thetas,
                const float* __restrict__ evecs,
                const float* __restrict__ evals,
                const float* __restrict__ sreal,
                const float* __restrict__ simag,
                float* __restrict__ out)
{
    extern __shared__ char smem[];
    const int t = threadIdx.x, w = t >> 5, lane = t & 31;
    const int b0 = blockIdx.x;
    const int g = lane >> 2, tg = lane & 3;

    // scratch overlay in A1 (dead until step-0 epilogue, which is post-sync)
    float* Vs = reinterpret_cast<float*>(smem + OFF_A1);   // stride 17
    float* cs = Vs + 288;
    float* sn = Vs + 336;

    if (t < 256) Vs[(t >> 4) * 17 + (t & 15)] = evecs[t];
    if (t >= 256 && t < 304) {
        int u = t - 256;
        int gg = u >> 4, m = u & 15;
        float s, c;
        sincosf(thetas[gg] * evals[m], &s, &c);
        cs[gg * 16 + m] = c;
        sn[gg * 16 + m] = s;
    }
    __syncthreads();

    // ---- gate build: split tables gsh/gsl[g][c*16+k] = (Urh,Uih)/(Url,Uil)
    if (t < 256) {
        int k = t >> 4, c = t & 15;
        float2* GH = reinterpret_cast<float2*>(smem + OFF_GSH);
        float2* GL = reinterpret_cast<float2*>(smem + OFF_GSL);
        #pragma unroll
        for (int gt = 0; gt < 3; gt++) {
            float ar = 0.f, ai = 0.f;
            #pragma unroll
            for (int m = 0; m < 16; m++) {
                float p = Vs[k * 17 + m] * Vs[c * 17 + m];
                ar += p * cs[gt * 16 + m];
                ai += p * sn[gt * 16 + m];
            }
            float Ur = ar, Ui = -ai;
            float urh, url, uih, uil;
            bsplit(Ur, urh, url);
            bsplit(Ui, uih, uil);
            GH[gt * 256 + c * 16 + k] = make_float2(urh, uih);
            GL[gt * 256 + c * 16 + k] = make_float2(url, uil);
        }
    }

    // ---- A0 build: row j = t>>1, complex cols ch*8..ch*8+7 ----
    {
        int row = t >> 1, ch = t & 1;
        const float* xr = sreal + b0 * DIM + row * 16 + ch * 8;
        const float* xi = simag + b0 * DIM + row * 16 + ch * 8;
        float4 r0 = *reinterpret_cast<const float4*>(xr);
        float4 r1 = *reinterpret_cast<const float4*>(xr + 4);
        float4 i0 = *reinterpret_cast<const float4*>(xi);
        float4 i1 = *reinterpret_cast<const float4*>(xi + 4);
        float vr[8] = { r0.x, r0.y, r0.z, r0.w, r1.x, r1.y, r1.z, r1.w };
        float vi[8] = { i0.x, i0.y, i0.z, i0.w, i1.x, i1.y, i1.z, i1.w };
        char* A0 = smem + OFF_A0 + row * ROWB;
        #pragma unroll
        for (int cc = 0; cc < 8; cc++) {
            int c = ch * 8 + cc;
            float hr, lr, hj, lj;
            bsplit(vr[cc], hr, lr);
            bsplit(vi[cc], hj, lj);
            *reinterpret_cast<u32*>(A0 + c * 4)      = pbf2(hr, hj);
            *reinterpret_cast<u32*>(A0 + 64 + c * 4) = pbf2(lr, lj);
        }
    }
    __syncthreads();

    const float2* GH = reinterpret_cast<const float2*>(smem + OFF_GSH);
    const float2* GL = reinterpret_cast<const float2*>(smem + OFF_GSL);
    const int s_par = g & 1, gh = g >> 1;

    // ldmatrix lane address (per A buffer): row 16w + (lane&15), col-halves
    const u32 lrow = 16 * w + (lane & 15);
    const u32 lcol = (lane >> 4) * 16;    // byte offset of 8-col half

    #pragma unroll
    for (int s = 0; s < 3; s++) {
        const int gate = 2 - s;

        // ---- B fragments (same for all warps) ----
        u32 bh[4][2][2], bl[4][2][2];     // [nt][kc][reg]
        #pragma unroll
        for (int nt = 0; nt < 4; nt++) {
            int kap = nt * 4 + gh;
            #pragma unroll
            for (int kc = 0; kc < 2; kc++)
                #pragma unroll
                for (int h = 0; h < 2; h++) {
                    int c = kc * 8 + tg + 4 * h;
                    float2 H = GH[gate * 256 + c * 16 + kap];
                    float2 L = GL[gate * 256 + c * 16 + kap];
                    bh[nt][kc][h] = s_par ? pbf2(H.y, H.x) : pbf2(H.x, -H.y);
                    bl[nt][kc][h] = s_par ? pbf2(L.y, L.x) : pbf2(L.x, -L.y);
                }
        }

        // ---- A fragments ----
        const u32 abase = smem_u32(smem) + ((s == 1) ? OFF_A1 : OFF_A0)
                        + lrow * ROWB + lcol;
        u32 ah0[4], ah1[4], al0[4], al1[4];
        ldm4(ah0, abase);
        ldm4(ah1, abase + 32);
        ldm4(al0, abase + 64);
        ldm4(al1, abase + 96);

        // ---- MMAs ----
        float D[4][4];
        #pragma unroll
        for (int nt = 0; nt < 4; nt++) {
            #pragma unroll
            for (int i = 0; i < 4; i++) D[nt][i] = 0.f;
            mma16816(D[nt], ah0, bh[nt][0][0], bh[nt][0][1]);
            mma16816(D[nt], ah1, bh[nt][1][0], bh[nt][1][1]);
            mma16816(D[nt], al0, bh[nt][0][0], bh[nt][0][1]);
            mma16816(D[nt], al1, bh[nt][1][0], bh[nt][1][1]);
            mma16816(D[nt], ah0, bl[nt][0][0], bl[nt][0][1]);
            mma16816(D[nt], ah1, bl[nt][1][0], bl[nt][1][1]);
        }

        // ---- epilogue ----
        if (s < 2) {
            char* ob = smem + ((s == 0) ? OFF_A1 : OFF_A0);
            #pragma unroll
            for (int nt = 0; nt < 4; nt++) {
                int kap = nt * 4 + tg;
                #pragma unroll
                for (int rr = 0; rr < 2; rr++) {
                    int j = 16 * w + g + 8 * rr;
                    float yr = D[nt][2 * rr], yi = D[nt][2 * rr + 1];
                    int rp, col;
                    if (s == 0) { rp = (j & 0xF0) | kap; col = j & 15; }
                    else        { rp = (kap << 4) | (j & 15); col = j >> 4; }
                    float hr, lr, hj, lj;
                    bsplit(yr, hr, lr);
                    bsplit(yi, hj, lj);
                    char* rbase = ob + rp * ROWB + col * 4;
                    *reinterpret_cast<u32*>(rbase)      = pbf2(hr, hj);
                    *reinterpret_cast<u32*>(rbase + 64) = pbf2(lr, lj);
                }
            }
        } else {
            // final: stage [ka][j] float2 in A1 region for coalesced writeout
            float2* fj = reinterpret_cast<float2*>(smem + OFF_A1);
            #pragma unroll
            for (int nt = 0; nt < 4; nt++) {
                int kap = nt * 4 + tg;
                #pragma unroll
                for (int rr = 0; rr < 2; rr++) {
                    int j = 16 * w + g + 8 * rr;
                    fj[kap * 256 + j] =
                        make_float2(D[nt][2 * rr], D[nt][2 * rr + 1]);
                }
            }
        }
        __syncthreads();
    }

    // ---- coalesced writeout: warp w owns ka = w ----
    {
        const float2* fj = reinterpret_cast<const float2*>(smem + OFF_A1);
        float* outr = out + b0 * DIM;
        float* outi = out + (size_t)BATCH * DIM + b0 * DIM;
        #pragma unroll
        for (int i = 0; i < 8; i++) {
            int j = lane + 32 * i;
            float2 v = fj[w * 256 + j];
            outr[w * 256 + j] = v.x;
            outi[w * 256 + j] = v.y;
        }
    }
}

extern "C" void kernel_launch(void* const* d_in, const int* in_sizes, int n_in,
                              void* d_out, int out_size) {
    const float* thetas = (const float*)d_in[0];
    const float* evecs  = (const float*)d_in[1];
    const float* evals  = (const float*)d_in[2];
    const float* sreal  = (const float*)d_in[3];
    const float* simag  = (const float*)d_in[4];

    static bool attr_set = false;
    if (!attr_set) {
        cudaFuncSetAttribute(ulayer_mma,
                             cudaFuncAttributeMaxDynamicSharedMemorySize,
                             SMEM_BYTES);
        attr_set = true;
    }
    ulayer_mma<<<BATCH, 512, SMEM_BYTES>>>(thetas, evecs, evals,
                                           sreal, simag, (float*)d_out);
}

// round 17
// speedup vs baseline: 1.5923x; 1.5923x over previous
#include <cuda_runtime.h>
#include <cuda_bf16.h>

#define BATCH 128
#define DIM   4096

#define ROWB 144                 // bytes per A row (64B Ah + 64B Al + 16B pad)
#define OFF_A0 0                 // 256 * 144 = 36864
#define OFF_A1 36864
#define OFF_GH 73728             // 3 gates * 512 u32 = 6144 B
#define OFF_GL 79872             // 6144 B
#define SMEM_BYTES 86016

typedef unsigned int u32;

__device__ __forceinline__ u32 smem_u32(const void* p) {
    u32 a;
    asm("{ .reg .u64 t; cvta.to.shared.u64 t, %1; cvt.u32.u64 %0, t; }"
        : "=r"(a) : "l"(p));
    return a;
}
__device__ __forceinline__ u32 pbf2(float lo, float hi) {
    __nv_bfloat162 h = __floats2bfloat162_rn(lo, hi);   // lo -> low 16 bits
    return *reinterpret_cast<u32*>(&h);
}
__device__ __forceinline__ void bsplit(float v, float& hi, float& lo) {
    __nv_bfloat16 h = __float2bfloat16(v);
    hi = __bfloat162float(h);
    lo = v - hi;                                        // exact in f32
}
__device__ __forceinline__ void ldm4(u32* r, u32 addr) {
    asm volatile(
        "ldmatrix.sync.aligned.m8n8.x4.shared.b16 {%0,%1,%2,%3}, [%4];"
        : "=r"(r[0]), "=r"(r[1]), "=r"(r[2]), "=r"(r[3]) : "r"(addr));
}
__device__ __forceinline__ void mma16816(float* d, const u32* a,
                                         u32 b0, u32 b1) {
    asm volatile(
        "mma.sync.aligned.m16n8k16.row.col.f32.bf16.bf16.f32 "
        "{%0,%1,%2,%3}, {%4,%5,%6,%7}, {%8,%9}, {%0,%1,%2,%3};"
        : "+f"(d[0]), "+f"(d[1]), "+f"(d[2]), "+f"(d[3])
        : "r"(a[0]), "r"(a[1]), "r"(a[2]), "r"(a[3]), "r"(b0), "r"(b1));
}

// Real embedding of complex 16x16 U into 32x32 W (verified in R16):
//   W[2c][2k]=Ur, W[2c+1][2k]=-Ui, W[2c][2k+1]=Ui, W[2c+1][2k+1]=Ur
// B-fragment tables are pre-permuted to lane order:
//   GH32[gate*512 + slot*32 + (4*gh+tg)*2 + s_par], slot=((nt*2+kc)*2+h)
// so each fragment load is one conflict-free LDS.32 (banks 0..31).

__global__ __launch_bounds__(512, 1)
void ulayer_mma(const float* __restrict__ thetas,
                const float* __restrict__ evecs,
                const float* __restrict__ evals,
                const float* __restrict__ sreal,
                const float* __restrict__ simag,
                float* __restrict__ out)
{
    extern __shared__ char smem[];
    const int t = threadIdx.x, w = t >> 5, lane = t & 31;
    const int b0 = blockIdx.x;
    const int g = lane >> 2, tg = lane & 3;

    // scratch overlay in A1 (dead until step-0 epilogue, post-sync)
    float* Vs = reinterpret_cast<float*>(smem + OFF_A1);   // stride 17
    float* cs = Vs + 288;
    float* sn = Vs + 336;

    if (t < 256) Vs[(t >> 4) * 17 + (t & 15)] = evecs[t];
    if (t >= 256 && t < 304) {
        int u = t - 256;
        int gg = u >> 4, m = u & 15;
        float s, c;
        sincosf(thetas[gg] * evals[m], &s, &c);
        cs[gg * 16 + m] = c;
        sn[gg * 16 + m] = s;
    }
    __syncthreads();

    // ---- gate build -> pre-permuted pre-packed fragment tables ----
    if (t < 256) {
        int k = t >> 4, c = t & 15;      // k = kap (n), c = complex K-col
        u32* GH32 = reinterpret_cast<u32*>(smem + OFF_GH);
        u32* GL32 = reinterpret_cast<u32*>(smem + OFF_GL);
        int slot   = ((k >> 2) * 2 + (c >> 3)) * 2 + ((c >> 2) & 1);
        int lane16 = 4 * (k & 3) + (c & 3);
        int base = slot * 32 + lane16 * 2;
        #pragma unroll
        for (int gt = 0; gt < 3; gt++) {
            float ar = 0.f, ai = 0.f;
            #pragma unroll
            for (int m = 0; m < 16; m++) {
                float p = Vs[k * 17 + m] * Vs[c * 17 + m];
                ar += p * cs[gt * 16 + m];
                ai += p * sn[gt * 16 + m];
            }
            float Ur = ar, Ui = -ai;
            float urh, url, uih, uil;
            bsplit(Ur, urh, url);
            bsplit(Ui, uih, uil);
            GH32[gt * 512 + base + 0] = pbf2(urh, -uih);   // s_par = 0
            GH32[gt * 512 + base + 1] = pbf2(uih, urh);    // s_par = 1
            GL32[gt * 512 + base + 0] = pbf2(url, -uil);
            GL32[gt * 512 + base + 1] = pbf2(uil, url);
        }
    }

    // ---- A0 build: row j = t>>1, complex cols ch*8..ch*8+7 ----
    {
        int row = t >> 1, ch = t & 1;
        const float* xr = sreal + b0 * DIM + row * 16 + ch * 8;
        const float* xi = simag + b0 * DIM + row * 16 + ch * 8;
        float4 r0 = *reinterpret_cast<const float4*>(xr);
        float4 r1 = *reinterpret_cast<const float4*>(xr + 4);
        float4 i0 = *reinterpret_cast<const float4*>(xi);
        float4 i1 = *reinterpret_cast<const float4*>(xi + 4);
        float vr[8] = { r0.x, r0.y, r0.z, r0.w, r1.x, r1.y, r1.z, r1.w };
        float vi[8] = { i0.x, i0.y, i0.z, i0.w, i1.x, i1.y, i1.z, i1.w };
        char* A0 = smem + OFF_A0 + row * ROWB;
        #pragma unroll
        for (int cc = 0; cc < 8; cc++) {
            int c = ch * 8 + cc;
            float hr, lr, hj, lj;
            bsplit(vr[cc], hr, lr);
            bsplit(vi[cc], hj, lj);
            *reinterpret_cast<u32*>(A0 + c * 4)      = pbf2(hr, hj);
            *reinterpret_cast<u32*>(A0 + 64 + c * 4) = pbf2(lr, lj);
        }
    }
    __syncthreads();

    const u32* GH32 = reinterpret_cast<const u32*>(smem + OFF_GH);
    const u32* GL32 = reinterpret_cast<const u32*>(smem + OFF_GL);
    const int s_par = g & 1, gh = g >> 1;
    const int lidx = (4 * gh + tg) * 2 + s_par;   // 0..31 — bank = lane-unique

    const u32 lrow = 16 * w + (lane & 15);
    const u32 lcol = (lane >> 4) * 16;

    #pragma unroll
    for (int s = 0; s < 3; s++) {
        const int gate = 2 - s;
        const u32* GHg = GH32 + gate * 512 + lidx;
        const u32* GLg = GL32 + gate * 512 + lidx;

        // ---- A fragments ----
        const u32 abase = smem_u32(smem) + ((s == 1) ? OFF_A1 : OFF_A0)
                        + lrow * ROWB + lcol;
        u32 ah0[4], ah1[4], al0[4], al1[4];
        ldm4(ah0, abase);
        ldm4(ah1, abase + 32);
        ldm4(al0, abase + 64);
        ldm4(al1, abase + 96);

        // ---- MMAs with conflict-free single-load B fragments ----
        float D[4][4];
        #pragma unroll
        for (int nt = 0; nt < 4; nt++) {
            // slot = ((nt*2+kc)*2+h) ; offset = slot*32
            u32 bh00 = GHg[((nt * 2 + 0) * 2 + 0) * 32];
            u32 bh01 = GHg[((nt * 2 + 0) * 2 + 1) * 32];
            u32 bh10 = GHg[((nt * 2 + 1) * 2 + 0) * 32];
            u32 bh11 = GHg[((nt * 2 + 1) * 2 + 1) * 32];
            u32 bl00 = GLg[((nt * 2 + 0) * 2 + 0) * 32];
            u32 bl01 = GLg[((nt * 2 + 0) * 2 + 1) * 32];
            u32 bl10 = GLg[((nt * 2 + 1) * 2 + 0) * 32];
            u32 bl11 = GLg[((nt * 2 + 1) * 2 + 1) * 32];
            #pragma unroll
            for (int i = 0; i < 4; i++) D[nt][i] = 0.f;
            mma16816(D[nt], ah0, bh00, bh01);
            mma16816(D[nt], ah1, bh10, bh11);
            mma16816(D[nt], al0, bh00, bh01);
            mma16816(D[nt], al1, bh10, bh11);
            mma16816(D[nt], ah0, bl00, bl01);
            mma16816(D[nt], ah1, bl10, bl11);
        }

        // ---- epilogue ----
        if (s < 2) {
            char* ob = smem + ((s == 0) ? OFF_A1 : OFF_A0);
            #pragma unroll
            for (int nt = 0; nt < 4; nt++) {
                int kap = nt * 4 + tg;
                #pragma unroll
                for (int rr = 0; rr < 2; rr++) {
                    int j = 16 * w + g + 8 * rr;
                    float yr = D[nt][2 * rr], yi = D[nt][2 * rr + 1];
                    int rp, col;
                    if (s == 0) { rp = (j & 0xF0) | kap; col = j & 15; }
                    else        { rp = (kap << 4) | (j & 15); col = j >> 4; }
                    float hr, lr, hj, lj;
                    bsplit(yr, hr, lr);
                    bsplit(yi, hj, lj);
                    char* rbase = ob + rp * ROWB + col * 4;
                    *reinterpret_cast<u32*>(rbase)      = pbf2(hr, hj);
                    *reinterpret_cast<u32*>(rbase + 64) = pbf2(lr, lj);
                }
            }
        } else {
            // final: stage [ka][j] float2 in A1 region for coalesced writeout
            float2* fj = reinterpret_cast<float2*>(smem + OFF_A1);
            #pragma unroll
            for (int nt = 0; nt < 4; nt++) {
                int kap = nt * 4 + tg;
                #pragma unroll
                for (int rr = 0; rr < 2; rr++) {
                    int j = 16 * w + g + 8 * rr;
                    fj[kap * 256 + j] =
                        make_float2(D[nt][2 * rr], D[nt][2 * rr + 1]);
                }
            }
        }
        __syncthreads();
    }

    // ---- coalesced writeout: warp w owns ka = w ----
    {
        const float2* fj = reinterpret_cast<const float2*>(smem + OFF_A1);
        float* outr = out + b0 * DIM;
        float* outi = out + (size_t)BATCH * DIM + b0 * DIM;
        #pragma unroll
        for (int i = 0; i < 8; i++) {
            int j = lane + 32 * i;
            float2 v = fj[w * 256 + j];
            outr[w * 256 + j] = v.x;
            outi[w * 256 + j] = v.y;
        }
    }
}

extern "C" void kernel_launch(void* const* d_in, const int* in_sizes, int n_in,
                              void* d_out, int out_size) {
    const float* thetas = (const float*)d_in[0];
    const float* evecs  = (const float*)d_in[1];
    const float* evals  = (const float*)d_in[2];
    const float* sreal  = (const float*)d_in[3];
    const float* simag  = (const float*)d_in[4];

    static bool attr_set = false;
    if (!attr_set) {
        cudaFuncSetAttribute(ulayer_mma,
                             cudaFuncAttributeMaxDynamicSharedMemorySize,
                             SMEM_BYTES);
        attr_set = true;
    }
    ulayer_mma<<<BATCH, 512, SMEM_BYTES>>>(thetas, evecs, evals,
                                           sreal, simag, (float*)d_out);
}